// round 11
// baseline (speedup 1.0000x reference)
#include <cuda_runtime.h>
#include <cuda_fp16.h>
#include <cstdint>

// ===================== problem dims (fixed) =====================
#define M_DIM 8192
#define N_DIM 4096
#define K_DIM 4096

// CTA tile 128(M) x 128(N), K-stage 64 halves (128B rows, SW128 swizzle)
// 2 CTAs per SM (cross-CTA overlap hides per-CTA pipeline bubbles).
#define TILE_M 128
#define TILE_N 128
#define KT 64
#define NK (K_DIM / KT)            // 64
#define STAGES 3
#define NTHREADS 128               // 4 warps: 2(M) x 2(N), warp tile 64x64

// ===================== static fp16 scratch (inputs arrive as f32) ==========
__device__ __half g_A16[(size_t)M_DIM * K_DIM];   // 64 MiB
__device__ __half g_W16[(size_t)N_DIM * K_DIM];   // 32 MiB

// ===================== SMEM layout (bytes) ======================
#define SM_FULL(s)  ((s) * 8)            // 0..23
#define SM_EMPTY(s) (24 + (s) * 8)       // 24..47
#define SM_BIAS 512                      // 512 B (128 f32)
#define SM_STAGE0 1024
#define A_STAGE_BYTES (TILE_M * 128)     // 16384
#define B_STAGE_BYTES (TILE_N * 128)     // 16384
#define STAGE_BYTES (A_STAGE_BYTES + B_STAGE_BYTES)   // 32768
#define SM_A(s) (SM_STAGE0 + (s) * STAGE_BYTES)
#define SM_B(s) (SM_A(s) + A_STAGE_BYTES)
#define SMEM_TOTAL (SM_STAGE0 + STAGES * STAGE_BYTES) // 99328 (x2 CTA = 198656)

// ===================== device helpers =====================
static __device__ __forceinline__ uint32_t smem_u32(const void* p) {
    uint32_t a;
    asm("{ .reg .u64 t; cvta.to.shared.u64 t, %1; cvt.u32.u64 %0, t; }"
        : "=r"(a) : "l"(p));
    return a;
}

static __device__ __forceinline__ uint32_t sw128(uint32_t off) {
    return off ^ ((off >> 3) & 0x70);
}

static __device__ __forceinline__ void cp_async16(uint32_t saddr, const void* gaddr) {
    asm volatile("cp.async.cg.shared.global [%0], [%1], 16;"
        :: "r"(saddr), "l"(gaddr) : "memory");
}

#define MBARRIER_INIT(addr, cnt) \
    asm volatile("mbarrier.init.shared.b64 [%0], %1;" \
        :: "r"((uint32_t)(addr)), "r"((uint32_t)(cnt)) : "memory")

#define MBARRIER_ARRIVE(addr) \
    asm volatile("mbarrier.arrive.shared.b64 _, [%0];" \
        :: "r"((uint32_t)(addr)) : "memory")

// arrive (counting against the INIT count: .noinc) when all this thread's
// prior cp.asyncs have completed.
#define CPASYNC_MBAR_ARRIVE(addr) \
    asm volatile("cp.async.mbarrier.arrive.noinc.shared::cta.b64 [%0];" \
        :: "r"((uint32_t)(addr)) : "memory")

#define MBARRIER_WAIT_PARITY(addr, parity) do {                                   \
    uint32_t _mbar = (uint32_t)(addr);                                            \
    uint32_t _par  = (uint32_t)(parity);                                          \
    uint32_t _done;                                                               \
    asm volatile(                                                                 \
        "{\n\t.reg .pred p;\n\t"                                                  \
        "mbarrier.try_wait.parity.acquire.cta.shared::cta.b64 p, [%1], %2;\n\t"   \
        "selp.b32 %0, 1, 0, p;\n\t}"                                              \
        : "=r"(_done) : "r"(_mbar), "r"(_par) : "memory");                        \
    if (!_done) {                                                                 \
        asm volatile(                                                             \
            "{\n\t.reg .pred P1;\n\t"                                             \
            "WAIT_LOOP_%=:\n\t"                                                   \
            "mbarrier.try_wait.parity.acquire.cta.shared::cta.b64 P1, [%0], %1, 0x989680;\n\t" \
            "@P1 bra.uni WAIT_DONE_%=;\n\t"                                       \
            "bra.uni WAIT_LOOP_%=;\n\t"                                           \
            "WAIT_DONE_%=:\n\t}"                                                  \
            :: "r"(_mbar), "r"(_par) : "memory");                                 \
    }                                                                             \
} while (0)

static __device__ __forceinline__ void ldsm_x4(uint32_t addr,
    uint32_t& r0, uint32_t& r1, uint32_t& r2, uint32_t& r3) {
    asm volatile("ldmatrix.sync.aligned.m8n8.x4.shared.b16 {%0,%1,%2,%3}, [%4];"
        : "=r"(r0), "=r"(r1), "=r"(r2), "=r"(r3) : "r"(addr));
}

static __device__ __forceinline__ void mma16816(
    float& c0, float& c1, float& c2, float& c3,
    uint32_t a0, uint32_t a1, uint32_t a2, uint32_t a3,
    uint32_t b0, uint32_t b1) {
    asm volatile(
        "mma.sync.aligned.m16n8k16.row.col.f32.f16.f16.f32 "
        "{%0,%1,%2,%3}, {%4,%5,%6,%7}, {%8,%9}, {%0,%1,%2,%3};"
        : "+f"(c0), "+f"(c1), "+f"(c2), "+f"(c3)
        : "r"(a0), "r"(a1), "r"(a2), "r"(a3), "r"(b0), "r"(b1));
}

static __device__ __forceinline__ float h_round(float x) {
    return __half2float(__float2half_rn(x));
}

// ===================== fused f32 -> f16 conversion (single launch) =========
#define NA4 ((M_DIM * K_DIM) / 4)          // 8388608
#define NW4 ((N_DIM * K_DIM) / 4)          // 4194304
__global__ void __launch_bounds__(256) cvt_all_f32_to_f16(
    const float4* __restrict__ inA, const float4* __restrict__ inW,
    __half* __restrict__ oA, __half* __restrict__ oW) {
    const int i = blockIdx.x * blockDim.x + threadIdx.x;
    const float4* src; __half* dst; int j;
    if (i < NA4) { src = inA; dst = oA; j = i; }
    else         { src = inW; dst = oW; j = i - NA4; }
    const float4 v = src[j];
    const __half2 h0 = __floats2half2_rn(v.x, v.y);
    const __half2 h1 = __floats2half2_rn(v.z, v.w);
    uint2 pk;
    pk.x = reinterpret_cast<const uint32_t&>(h0);
    pk.y = reinterpret_cast<const uint32_t&>(h1);
    *(uint2*)(dst + (size_t)j * 4) = pk;
}

// ===================== GEMM kernel =====================
// 128 threads = 4 warps as 2(M) x 2(N); warp tile 64x64, f32 accumulate.
// 2 CTAs resident per SM. 3-stage cp.async ring with per-stage mbarrier
// full/empty. Parity via explicit LAP COUNTERS (R10 deadlock: XOR-on-wrap
// flipped producer parity one lap early).
//   load of slot s, lap L (L>=1) waits EMPTY(s) parity (L-1)&1
//   consume of slot s, lap L        waits FULL(s)  parity L&1
__global__ void __launch_bounds__(NTHREADS, 2) linear_f16_hmma(
    const float* __restrict__ bias,  // [4096] f32
    float* __restrict__ out)         // [8192, 4096] f32
{
    extern __shared__ char smem[];
    const uint32_t sb = smem_u32(smem);
    const int tid  = threadIdx.x;
    const int wid  = tid >> 5;
    const int lane = tid & 31;
    const int warp_m = wid & 1;      // 0..1
    const int warp_n = wid >> 1;     // 0..1

    const int ntile = blockIdx.x;    // 32
    const int mtile = blockIdx.y;    // 64
    const int m0 = mtile * TILE_M;
    const int n0 = ntile * TILE_N;

    // ---- init: mbarriers (tid 0), bias ----
    if (tid == 0) {
        #pragma unroll
        for (int s = 0; s < STAGES; ++s) {
            MBARRIER_INIT(sb + SM_FULL(s),  NTHREADS);
            MBARRIER_INIT(sb + SM_EMPTY(s), NTHREADS);
        }
    }
    if (tid < 32) {
        ((float4*)(smem + SM_BIAS))[tid] = ((const float4*)(bias + n0))[tid];
    }
    __syncthreads();   // barriers + bias visible; only CTA-wide sync in kernel

    const char* Abase = (const char*)(g_A16 + (size_t)m0 * K_DIM);
    const char* Bbase = (const char*)(g_W16 + (size_t)n0 * K_DIM);

    // -------- stage loader: 2048 x 16B chunks, 16 per thread --------
    auto load_stage = [&](int kt, int s) {
        const size_t kbyte = (size_t)kt * (KT * 2);
        const uint32_t a_s = sb + SM_A(s);
        const uint32_t b_s = sb + SM_B(s);
        #pragma unroll
        for (int i = 0; i < 16; ++i) {
            const int c = tid + i * NTHREADS;
            if (c < 1024) {                       // A: 128 rows x 8 chunks
                const int row = c >> 3, ci = c & 7;
                const char* g = Abase + (size_t)row * (K_DIM * 2) + kbyte + ci * 16;
                cp_async16(a_s + sw128((uint32_t)(row * 128 + ci * 16)), g);
            } else {                              // B: 128 rows x 8 chunks
                const int c2 = c - 1024;
                const int row = c2 >> 3, ci = c2 & 7;
                const char* g = Bbase + (size_t)row * (K_DIM * 2) + kbyte + ci * 16;
                cp_async16(b_s + sw128((uint32_t)(row * 128 + ci * 16)), g);
            }
        }
        CPASYNC_MBAR_ARRIVE(sb + SM_FULL(s));
    };

    // -------- f32 accumulators: warp tile 64(M) x 64(N) --------
    float acc[4][8][4];
    #pragma unroll
    for (int mf = 0; mf < 4; ++mf)
        #pragma unroll
        for (int nf = 0; nf < 8; ++nf)
            #pragma unroll
            for (int i = 0; i < 4; ++i) acc[mf][nf][i] = 0.f;

    // per-lane ldmatrix address components
    const int a_row  = warp_m * 64 + (lane & 15);
    const int a_koff = (lane >> 4) * 16;
    const int b_row  = warp_n * 64 + ((lane >> 4) << 3) + (lane & 7);
    const int b_koff = ((lane >> 3) & 1) * 16;

    // -------- prologue: fill 2 stages (slot 0 and 1, lap 0) --------
    load_stage(0, 0);
    load_stage(1, 1);

    // ring cursors with explicit lap counters
    int cs = 0, clap = 0;      // consumer: slot, lap
    int ps = 2, plap = 0;      // producer: slot, lap (of the load being issued)

    // -------- main loop: no __syncthreads --------
    for (int kt = 0; kt < NK; ++kt) {
        // produce stage kt+2 into slot ps (lap plap)
        const int ld = kt + 2;
        if (ld < NK) {
            if (plap >= 1) {   // slot had a previous lap: wait for its readers
                MBARRIER_WAIT_PARITY(sb + SM_EMPTY(ps), (plap - 1) & 1);
            }
            load_stage(ld, ps);
            if (++ps == STAGES) { ps = 0; ++plap; }
        }

        // consume stage kt (slot cs, lap clap)
        MBARRIER_WAIT_PARITY(sb + SM_FULL(cs), clap & 1);

        const uint32_t aB = sb + SM_A(cs);
        const uint32_t bB = sb + SM_B(cs);

        #pragma unroll
        for (int kk = 0; kk < 4; ++kk) {
            uint32_t a[4][4];
            #pragma unroll
            for (int mf = 0; mf < 4; ++mf) {
                const uint32_t addr = aB +
                    sw128((uint32_t)((a_row + mf * 16) * 128 + kk * 32 + a_koff));
                ldsm_x4(addr, a[mf][0], a[mf][1], a[mf][2], a[mf][3]);
            }
            uint32_t b[4][4];
            #pragma unroll
            for (int nf2 = 0; nf2 < 4; ++nf2) {
                const uint32_t addr = bB +
                    sw128((uint32_t)((b_row + nf2 * 16) * 128 + kk * 32 + b_koff));
                ldsm_x4(addr, b[nf2][0], b[nf2][1], b[nf2][2], b[nf2][3]);
            }
            #pragma unroll
            for (int mf = 0; mf < 4; ++mf) {
                #pragma unroll
                for (int nf = 0; nf < 8; ++nf) {
                    const uint32_t b0 = b[nf >> 1][(nf & 1) * 2 + 0];
                    const uint32_t b1 = b[nf >> 1][(nf & 1) * 2 + 1];
                    mma16816(acc[mf][nf][0], acc[mf][nf][1],
                             acc[mf][nf][2], acc[mf][nf][3],
                             a[mf][0], a[mf][1], a[mf][2], a[mf][3], b0, b1);
                }
            }
        }

        // done reading stage kt
        MBARRIER_ARRIVE(sb + SM_EMPTY(cs));
        if (++cs == STAGES) { cs = 0; ++clap; }
    }

    // -------- epilogue: bias add (f32), fp16 round, f32 store --------
    const float2* biasS = (const float2*)(smem + SM_BIAS);
    float2 bv[8];
    #pragma unroll
    for (int nf = 0; nf < 8; ++nf)
        bv[nf] = biasS[warp_n * 32 + nf * 4 + (lane & 3)];

    const int row0 = m0 + warp_m * 64 + (lane >> 2);
    const int col0 = n0 + warp_n * 64 + (lane & 3) * 2;

    #pragma unroll
    for (int mf = 0; mf < 4; ++mf) {
        #pragma unroll
        for (int nf = 0; nf < 8; ++nf) {
            const float bx = bv[nf].x, by = bv[nf].y;
            const int r = row0 + mf * 16;
            const int c = col0 + nf * 8;
            float2 lo, hi;
            lo.x = h_round(acc[mf][nf][0] + bx);
            lo.y = h_round(acc[mf][nf][1] + by);
            hi.x = h_round(acc[mf][nf][2] + bx);
            hi.y = h_round(acc[mf][nf][3] + by);
            *(float2*)(out + (size_t)r * N_DIM + c)       = lo;
            *(float2*)(out + (size_t)(r + 8) * N_DIM + c) = hi;
        }
    }
}

// ===================== host launcher =====================
extern "C" void kernel_launch(void* const* d_in, const int* in_sizes, int n_in,
                              void* d_out, int out_size) {
    (void)in_sizes; (void)n_in; (void)out_size;
    const float* x = (const float*)d_in[0];   // [8192,4096] f32
    const float* w = (const float*)d_in[1];   // [4096,4096] f32
    const float* b = (const float*)d_in[2];   // [4096] f32
    float* y = (float*)d_out;                 // [8192,4096] f32

    static __half* a16_ptr = nullptr;
    static __half* w16_ptr = nullptr;
    if (!a16_ptr) {
        cudaGetSymbolAddress((void**)&a16_ptr, g_A16);
        cudaGetSymbolAddress((void**)&w16_ptr, g_W16);
    }

    cvt_all_f32_to_f16<<<(NA4 + NW4) / 256, 256>>>(
        (const float4*)x, (const float4*)w, a16_ptr, w16_ptr);

    cudaFuncSetAttribute(linear_f16_hmma,
                         cudaFuncAttributeMaxDynamicSharedMemorySize, SMEM_TOTAL);
    dim3 grid(N_DIM / TILE_N, M_DIM / TILE_M);   // (32, 64)
    linear_f16_hmma<<<grid, NTHREADS, SMEM_TOTAL>>>(b, y);
}

// round 12
// speedup vs baseline: 1.0303x; 1.0303x over previous
#include <cuda_runtime.h>
#include <cuda_fp16.h>
#include <cstdint>

// ===================== problem dims (fixed) =====================
#define M_DIM 8192
#define N_DIM 4096
#define K_DIM 4096

// CTA tile 128(M) x 256(N), K-stage 64 halves (128B rows, SW128 swizzle)
// PERSISTENT CTAs: grid = #SMs, each CTA walks multiple tiles through one
// continuous 4-stage ring (pipeline never drains at tile boundaries).
#define TILE_M 128
#define TILE_N 256
#define KT 64
#define NK (K_DIM / KT)            // 64  (iterations per tile)
#define STAGES 4
#define NTHREADS 256               // 8 warps: 2(M) x 4(N), warp tile 64x64
#define NTILES 1024                // 64 mtiles x 16 ntiles

// ===================== static fp16 scratch (inputs arrive as f32) ==========
__device__ __half g_A16[(size_t)M_DIM * K_DIM];   // 64 MiB
__device__ __half g_W16[(size_t)N_DIM * K_DIM];   // 32 MiB

// ===================== SMEM layout (bytes) ======================
#define SM_FULL(s)  ((s) * 8)            // 0..31
#define SM_EMPTY(s) (32 + (s) * 8)       // 32..63
#define SM_STAGE0 1024
#define A_STAGE_BYTES (TILE_M * 128)     // 16384
#define B_STAGE_BYTES (TILE_N * 128)     // 32768
#define STAGE_BYTES (A_STAGE_BYTES + B_STAGE_BYTES)   // 49152
#define SM_A(s) (SM_STAGE0 + (s) * STAGE_BYTES)
#define SM_B(s) (SM_A(s) + A_STAGE_BYTES)
#define SMEM_TOTAL (SM_STAGE0 + STAGES * STAGE_BYTES) // 197632

// ===================== device helpers =====================
static __device__ __forceinline__ uint32_t smem_u32(const void* p) {
    uint32_t a;
    asm("{ .reg .u64 t; cvta.to.shared.u64 t, %1; cvt.u32.u64 %0, t; }"
        : "=r"(a) : "l"(p));
    return a;
}

static __device__ __forceinline__ uint32_t sw128(uint32_t off) {
    return off ^ ((off >> 3) & 0x70);
}

static __device__ __forceinline__ void cp_async16(uint32_t saddr, const void* gaddr) {
    asm volatile("cp.async.cg.shared.global [%0], [%1], 16;"
        :: "r"(saddr), "l"(gaddr) : "memory");
}

#define MBARRIER_INIT(addr, cnt) \
    asm volatile("mbarrier.init.shared.b64 [%0], %1;" \
        :: "r"((uint32_t)(addr)), "r"((uint32_t)(cnt)) : "memory")

#define MBARRIER_ARRIVE(addr) \
    asm volatile("mbarrier.arrive.shared.b64 _, [%0];" \
        :: "r"((uint32_t)(addr)) : "memory")

// arrive (counting against the INIT count: .noinc) when all this thread's
// prior cp.asyncs have completed.
#define CPASYNC_MBAR_ARRIVE(addr) \
    asm volatile("cp.async.mbarrier.arrive.noinc.shared::cta.b64 [%0];" \
        :: "r"((uint32_t)(addr)) : "memory")

#define MBARRIER_WAIT_PARITY(addr, parity) do {                                   \
    uint32_t _mbar = (uint32_t)(addr);                                            \
    uint32_t _par  = (uint32_t)(parity);                                          \
    uint32_t _done;                                                               \
    asm volatile(                                                                 \
        "{\n\t.reg .pred p;\n\t"                                                  \
        "mbarrier.try_wait.parity.acquire.cta.shared::cta.b64 p, [%1], %2;\n\t"   \
        "selp.b32 %0, 1, 0, p;\n\t}"                                              \
        : "=r"(_done) : "r"(_mbar), "r"(_par) : "memory");                        \
    if (!_done) {                                                                 \
        asm volatile(                                                             \
            "{\n\t.reg .pred P1;\n\t"                                             \
            "WAIT_LOOP_%=:\n\t"                                                   \
            "mbarrier.try_wait.parity.acquire.cta.shared::cta.b64 P1, [%0], %1, 0x989680;\n\t" \
            "@P1 bra.uni WAIT_DONE_%=;\n\t"                                       \
            "bra.uni WAIT_LOOP_%=;\n\t"                                           \
            "WAIT_DONE_%=:\n\t}"                                                  \
            :: "r"(_mbar), "r"(_par) : "memory");                                 \
    }                                                                             \
} while (0)

static __device__ __forceinline__ void ldsm_x4(uint32_t addr,
    uint32_t& r0, uint32_t& r1, uint32_t& r2, uint32_t& r3) {
    asm volatile("ldmatrix.sync.aligned.m8n8.x4.shared.b16 {%0,%1,%2,%3}, [%4];"
        : "=r"(r0), "=r"(r1), "=r"(r2), "=r"(r3) : "r"(addr));
}

static __device__ __forceinline__ void mma16816(
    float& c0, float& c1, float& c2, float& c3,
    uint32_t a0, uint32_t a1, uint32_t a2, uint32_t a3,
    uint32_t b0, uint32_t b1) {
    asm volatile(
        "mma.sync.aligned.m16n8k16.row.col.f32.f16.f16.f32 "
        "{%0,%1,%2,%3}, {%4,%5,%6,%7}, {%8,%9}, {%0,%1,%2,%3};"
        : "+f"(c0), "+f"(c1), "+f"(c2), "+f"(c3)
        : "r"(a0), "r"(a1), "r"(a2), "r"(a3), "r"(b0), "r"(b1));
}

static __device__ __forceinline__ float h_round(float x) {
    return __half2float(__float2half_rn(x));
}

// ===================== fused f32 -> f16 conversion (single launch) =========
#define NA4 ((M_DIM * K_DIM) / 4)          // 8388608
#define NW4 ((N_DIM * K_DIM) / 4)          // 4194304
__global__ void __launch_bounds__(256) cvt_all_f32_to_f16(
    const float4* __restrict__ inA, const float4* __restrict__ inW,
    __half* __restrict__ oA, __half* __restrict__ oW) {
    const int i = blockIdx.x * blockDim.x + threadIdx.x;
    const float4* src; __half* dst; int j;
    if (i < NA4) { src = inA; dst = oA; j = i; }
    else         { src = inW; dst = oW; j = i - NA4; }
    const float4 v = src[j];
    const __half2 h0 = __floats2half2_rn(v.x, v.y);
    const __half2 h1 = __floats2half2_rn(v.z, v.w);
    uint2 pk;
    pk.x = reinterpret_cast<const uint32_t&>(h0);
    pk.y = reinterpret_cast<const uint32_t&>(h1);
    *(uint2*)(dst + (size_t)j * 4) = pk;
}

// ===================== GEMM kernel (persistent) =====================
// 256 threads = 8 warps as 2(M) x 4(N); warp tile 64x64, f32 accumulate.
// Each CTA processes tiles {bid, bid+grid, ...} through ONE continuous
// 4-stage cp.async/mbarrier ring spanning tile boundaries: while tile t's
// last MMAs + epilogue run, stages of tile t+1 are already loading.
__global__ void __launch_bounds__(NTHREADS, 1) linear_f16_hmma(
    const float* __restrict__ bias,  // [4096] f32
    float* __restrict__ out)         // [8192, 4096] f32
{
    extern __shared__ char smem[];
    const uint32_t sb = smem_u32(smem);
    const int tid  = threadIdx.x;
    const int wid  = tid >> 5;
    const int lane = tid & 31;
    const int warp_m = wid & 1;      // 0..1
    const int warp_n = wid >> 1;     // 0..3
    const int bid  = blockIdx.x;
    const int nsm  = gridDim.x;

    // tiles handled by this CTA: bid, bid+nsm, ... < NTILES
    const int ntiles_cta = (NTILES - bid + nsm - 1) / nsm;
    const int niter = ntiles_cta * NK;

    // ---- init: mbarriers (tid 0) ----
    if (tid == 0) {
        #pragma unroll
        for (int s = 0; s < STAGES; ++s) {
            MBARRIER_INIT(sb + SM_FULL(s),  NTHREADS);
            MBARRIER_INIT(sb + SM_EMPTY(s), NTHREADS);
        }
    }
    __syncthreads();   // barriers visible; only CTA-wide sync in kernel

    const char* const Aall = (const char*)g_A16;
    const char* const Ball = (const char*)g_W16;

    // -------- stage loader for flat iteration `it`: 3072 x 16B chunks ------
    auto load_stage = [&](int it) {
        const int s  = it & (STAGES - 1);
        const int lt = it >> 6;                 // local tile index
        const int kt = it & (NK - 1);
        const int gt = bid + lt * nsm;          // global tile
        const int mt = gt >> 4, nt = gt & 15;
        const char* Abase = Aall + (size_t)(mt * TILE_M) * (K_DIM * 2);
        const char* Bbase = Ball + (size_t)(nt * TILE_N) * (K_DIM * 2);
        const size_t kbyte = (size_t)kt * (KT * 2);
        const uint32_t a_s = sb + SM_A(s);
        const uint32_t b_s = sb + SM_B(s);
        #pragma unroll
        for (int i = 0; i < 12; ++i) {
            const int c = tid + i * NTHREADS;
            if (c < 1024) {                       // A: 128 rows x 8 chunks
                const int row = c >> 3, ci = c & 7;
                const char* g = Abase + (size_t)row * (K_DIM * 2) + kbyte + ci * 16;
                cp_async16(a_s + sw128((uint32_t)(row * 128 + ci * 16)), g);
            } else {                              // B: 256 rows x 8 chunks
                const int c2 = c - 1024;
                const int row = c2 >> 3, ci = c2 & 7;
                const char* g = Bbase + (size_t)row * (K_DIM * 2) + kbyte + ci * 16;
                cp_async16(b_s + sw128((uint32_t)(row * 128 + ci * 16)), g);
            }
        }
        CPASYNC_MBAR_ARRIVE(sb + SM_FULL(s));
    };

    // -------- f32 accumulators: warp tile 64(M) x 64(N) --------
    float acc[4][8][4];
    #pragma unroll
    for (int mf = 0; mf < 4; ++mf)
        #pragma unroll
        for (int nf = 0; nf < 8; ++nf)
            #pragma unroll
            for (int i = 0; i < 4; ++i) acc[mf][nf][i] = 0.f;

    // per-lane ldmatrix address components
    const int a_row  = warp_m * 64 + (lane & 15);
    const int a_koff = (lane >> 4) * 16;
    const int b_row  = warp_n * 64 + ((lane >> 4) << 3) + (lane & 7);
    const int b_koff = ((lane >> 3) & 1) * 16;

    // -------- prologue: fill 3 stages --------
    if (0 < niter) load_stage(0);
    if (1 < niter) load_stage(1);
    if (2 < niter) load_stage(2);

    // -------- flat main loop over all tiles: ring never drains --------
    for (int it = 0; it < niter; ++it) {
        // produce iteration it+3 (slot last consumed as it-1)
        const int ld = it + 3;
        if (ld < niter) {
            if (ld >= STAGES) {   // slot has a previous lap to drain
                MBARRIER_WAIT_PARITY(sb + SM_EMPTY(ld & (STAGES - 1)),
                                     ((ld >> 2) - 1) & 1);
            }
            load_stage(ld);
        }

        // consume iteration it
        const int s = it & (STAGES - 1);
        MBARRIER_WAIT_PARITY(sb + SM_FULL(s), (it >> 2) & 1);

        const uint32_t aB = sb + SM_A(s);
        const uint32_t bB = sb + SM_B(s);

        #pragma unroll
        for (int kk = 0; kk < 4; ++kk) {
            uint32_t a[4][4];
            #pragma unroll
            for (int mf = 0; mf < 4; ++mf) {
                const uint32_t addr = aB +
                    sw128((uint32_t)((a_row + mf * 16) * 128 + kk * 32 + a_koff));
                ldsm_x4(addr, a[mf][0], a[mf][1], a[mf][2], a[mf][3]);
            }
            uint32_t b[4][4];
            #pragma unroll
            for (int nf2 = 0; nf2 < 4; ++nf2) {
                const uint32_t addr = bB +
                    sw128((uint32_t)((b_row + nf2 * 16) * 128 + kk * 32 + b_koff));
                ldsm_x4(addr, b[nf2][0], b[nf2][1], b[nf2][2], b[nf2][3]);
            }
            #pragma unroll
            for (int mf = 0; mf < 4; ++mf) {
                #pragma unroll
                for (int nf = 0; nf < 8; ++nf) {
                    const uint32_t b0 = b[nf >> 1][(nf & 1) * 2 + 0];
                    const uint32_t b1 = b[nf >> 1][(nf & 1) * 2 + 1];
                    mma16816(acc[mf][nf][0], acc[mf][nf][1],
                             acc[mf][nf][2], acc[mf][nf][3],
                             a[mf][0], a[mf][1], a[mf][2], a[mf][3], b0, b1);
                }
            }
        }

        // done reading this stage
        MBARRIER_ARRIVE(sb + SM_EMPTY(s));

        // -------- tile boundary: epilogue + acc reset --------
        if ((it & (NK - 1)) == NK - 1) {
            const int gt = bid + (it >> 6) * nsm;
            const int m0 = (gt >> 4) * TILE_M;
            const int n0 = (gt & 15) * TILE_N;

            const int row0 = m0 + warp_m * 64 + (lane >> 2);
            const int col0 = n0 + warp_n * 64 + (lane & 3) * 2;
            const int bcol = warp_n * 64 + (lane & 3) * 2;

            #pragma unroll
            for (int mf = 0; mf < 4; ++mf) {
                #pragma unroll
                for (int nf = 0; nf < 8; ++nf) {
                    const float2 bv = *(const float2*)(bias + n0 + bcol + nf * 8);
                    const int r = row0 + mf * 16;
                    const int c = col0 + nf * 8;
                    float2 lo, hi;
                    lo.x = h_round(acc[mf][nf][0] + bv.x);
                    lo.y = h_round(acc[mf][nf][1] + bv.y);
                    hi.x = h_round(acc[mf][nf][2] + bv.x);
                    hi.y = h_round(acc[mf][nf][3] + bv.y);
                    *(float2*)(out + (size_t)r * N_DIM + c)       = lo;
                    *(float2*)(out + (size_t)(r + 8) * N_DIM + c) = hi;
                    acc[mf][nf][0] = 0.f; acc[mf][nf][1] = 0.f;
                    acc[mf][nf][2] = 0.f; acc[mf][nf][3] = 0.f;
                }
            }
        }
    }
}

// ===================== host launcher =====================
extern "C" void kernel_launch(void* const* d_in, const int* in_sizes, int n_in,
                              void* d_out, int out_size) {
    (void)in_sizes; (void)n_in; (void)out_size;
    const float* x = (const float*)d_in[0];   // [8192,4096] f32
    const float* w = (const float*)d_in[1];   // [4096,4096] f32
    const float* b = (const float*)d_in[2];   // [4096] f32
    float* y = (float*)d_out;                 // [8192,4096] f32

    static __half* a16_ptr = nullptr;
    static __half* w16_ptr = nullptr;
    static int nsm = 0;
    if (!a16_ptr) {
        cudaGetSymbolAddress((void**)&a16_ptr, g_A16);
        cudaGetSymbolAddress((void**)&w16_ptr, g_W16);
        cudaDeviceGetAttribute(&nsm, cudaDevAttrMultiProcessorCount, 0);
        if (nsm <= 0 || nsm > NTILES) nsm = 148;
    }

    cvt_all_f32_to_f16<<<(NA4 + NW4) / 256, 256>>>(
        (const float4*)x, (const float4*)w, a16_ptr, w16_ptr);

    cudaFuncSetAttribute(linear_f16_hmma,
                         cudaFuncAttributeMaxDynamicSharedMemorySize, SMEM_TOTAL);
    linear_f16_hmma<<<nsm, NTHREADS, SMEM_TOTAL>>>(b, y);
}